// round 7
// baseline (speedup 1.0000x reference)
#include <cuda_runtime.h>
#include <math.h>

#define Bb 8
#define Nn 4096
#define Cc 256
#define Kk 32
#define ROWS (Bb * Nn)

// Scratch (allocation-free rule: __device__ globals)
__device__ float g_feat[ROWS * Cc];   // 32 MB
__device__ float g_pos [ROWS * Cc];   // 32 MB
__device__ float g_tkv [ROWS * Kk];   // 4 MB
__device__ int   g_tki [ROWS * Kk];   // 4 MB

// ---------------------------------------------------------------------------
// Kernel 1: feat_pos = x @ W^T + bias, routed into g_feat (cols 0..255) and
// g_pos (cols 256..511). Sequential k-order FMA chain per output element
// (correlates rounding with the reference GEMM).
// ---------------------------------------------------------------------------
__global__ __launch_bounds__(256) void k_gemm(const float* __restrict__ x,
                                              const float* __restrict__ W,
                                              const float* __restrict__ bias) {
    __shared__ float as[128][17];
    __shared__ float bs[128][17];
    const int t  = threadIdx.x;
    const int tx = t & 15;
    const int ty = t >> 4;
    const int m0 = blockIdx.x * 128;
    const int n0 = blockIdx.y * 128;
    const float* xa = x + (size_t)m0 * Cc;
    const float* wb = W + (size_t)n0 * Cc;

    float acc[8][8];
#pragma unroll
    for (int j = 0; j < 8; j++)
#pragma unroll
        for (int i = 0; i < 8; i++) acc[j][i] = 0.f;

    for (int c0 = 0; c0 < Cc; c0 += 16) {
#pragma unroll
        for (int r = 0; r < 8; r++) {
            int lin = t + r * 256;         // 0..2047
            int row = lin >> 4;            // 0..127
            int cc  = lin & 15;            // 0..15
            as[row][cc] = xa[row * Cc + c0 + cc];
            bs[row][cc] = wb[row * Cc + c0 + cc];
        }
        __syncthreads();
#pragma unroll
        for (int c = 0; c < 16; c++) {
            float av[8], bv[8];
#pragma unroll
            for (int j = 0; j < 8; j++) av[j] = as[ty + 16 * j][c];
#pragma unroll
            for (int i = 0; i < 8; i++) bv[i] = bs[tx + 16 * i][c];
#pragma unroll
            for (int j = 0; j < 8; j++)
#pragma unroll
                for (int i = 0; i < 8; i++) acc[j][i] = fmaf(av[j], bv[i], acc[j][i]);
        }
        __syncthreads();
    }

#pragma unroll
    for (int j = 0; j < 8; j++) {
        int row = m0 + ty + 16 * j;
#pragma unroll
        for (int i = 0; i < 8; i++) {
            int col = n0 + tx + 16 * i;
            float v = acc[j][i] + bias[col];
            if (col < Cc) g_feat[(size_t)row * Cc + col] = v;
            else          g_pos [(size_t)row * Cc + (col - Cc)] = v;
        }
    }
}

// ---------------------------------------------------------------------------
// Kernel 2: L2-normalize each row of g_pos. 8 warps/block, one row per warp.
// DIVIDE by norm (matches reference pos / max(norm,1e-12) rounding exactly,
// unlike multiply-by-reciprocal).
// ---------------------------------------------------------------------------
__global__ __launch_bounds__(256) void k_normalize() {
    const int row  = blockIdx.x * 8 + (threadIdx.x >> 5);
    const int lane = threadIdx.x & 31;
    float4* p = reinterpret_cast<float4*>(g_pos + (size_t)row * Cc);
    float4 a = p[lane];
    float4 b = p[lane + 32];
    float s = a.x * a.x + a.y * a.y + a.z * a.z + a.w * a.w
            + b.x * b.x + b.y * b.y + b.z * b.z + b.w * b.w;
#pragma unroll
    for (int o = 16; o > 0; o >>= 1) s += __shfl_xor_sync(0xffffffffu, s, o);
    float nrm = fmaxf(sqrtf(s), 1e-12f);
    a.x /= nrm; a.y /= nrm; a.z /= nrm; a.w /= nrm;
    b.x /= nrm; b.y /= nrm; b.z /= nrm; b.w /= nrm;
    p[lane]      = a;
    p[lane + 32] = b;
}

// ---------------------------------------------------------------------------
// Kernel 3: fused sim GEMM + streaming top-32.
// Block = 32 query rows x all 4096 keys of one batch. 256 threads.
// Accumulation: STRICT sequential k-order single-FMA chain per sim element
// (explicit fmaf; matches cuBLAS/XLA SIMT sgemm rounding bit-for-bit when
// inputs match — do NOT re-associate).
// Top-k tie handling matches jax.lax.top_k: on equal values the LOWER index
// wins, so eviction picks the LARGEST index among equal minima.
// ---------------------------------------------------------------------------
__global__ __launch_bounds__(256) void k_sim_topk() {
    extern __shared__ float sm[];
    float* qs     = sm;            // [32][256]
    float* ks     = sm + 8192;     // [128][68]
    float* simbuf = sm + 16896;    // [32][129]
    float* tkv    = sm + 21024;    // [32][33]
    int*   tki    = (int*)(sm + 22080);  // [32][33]

    const int t   = threadIdx.x;
    const int b   = blockIdx.y;
    const int q0g = blockIdx.x * 32;  // query row base within batch
    const float* __restrict__ pos = g_pos + (size_t)b * Nn * Cc;

    // Stage query tile (contiguous copy, coalesced)
    for (int lin = t; lin < 32 * Cc; lin += 256)
        qs[lin] = pos[(size_t)q0g * Cc + lin];

    // Per-query top-k state (one owner thread per query)
    float mv = -1e30f;     // current min value in buffer
    int   mp = 0;          // its slot
    int   mi = 0x7fffffff; // its candidate index (for tie-break)
    if (t < 32) {
#pragma unroll
        for (int s = 0; s < 32; s++) { tkv[t * 33 + s] = -1e30f; tki[t * 33 + s] = 0x7fffffff; }
    }

    const int qg = t >> 5;   // 0..7
    const int kg = t & 31;   // 0..31

    for (int kt = 0; kt < Nn; kt += 128) {
        float acc[4][4];
#pragma unroll
        for (int j = 0; j < 4; j++)
#pragma unroll
            for (int i = 0; i < 4; i++) acc[j][i] = 0.f;

        for (int cc = 0; cc < Cc; cc += 64) {
            __syncthreads();   // protects ks reuse + simbuf from prior top-k scan
            // Stage key chunk: 128 keys x 64 channels
#pragma unroll
            for (int r = 0; r < 8; r++) {
                int lin = t + r * 256;            // 0..2047 float4 units
                int kk  = lin >> 4;               // 0..127
                int c4  = (lin & 15) << 2;        // 0..60
                float4 v = *(const float4*)(pos + (size_t)(kt + kk) * Cc + cc + c4);
                *(float4*)(ks + kk * 68 + c4) = v;
            }
            __syncthreads();
#pragma unroll
            for (int c = 0; c < 64; c += 4) {
                float4 kv0 = *(const float4*)(ks + (kg      ) * 68 + c);
                float4 kv1 = *(const float4*)(ks + (kg + 32 ) * 68 + c);
                float4 kv2 = *(const float4*)(ks + (kg + 64 ) * 68 + c);
                float4 kv3 = *(const float4*)(ks + (kg + 96 ) * 68 + c);
#pragma unroll
                for (int j = 0; j < 4; j++) {
                    float4 qv = *(const float4*)(qs + (qg * 4 + j) * Cc + cc + c);
                    // strict sequential k-order chains (one per sim element)
                    acc[j][0] = fmaf(qv.x, kv0.x, acc[j][0]);
                    acc[j][0] = fmaf(qv.y, kv0.y, acc[j][0]);
                    acc[j][0] = fmaf(qv.z, kv0.z, acc[j][0]);
                    acc[j][0] = fmaf(qv.w, kv0.w, acc[j][0]);
                    acc[j][1] = fmaf(qv.x, kv1.x, acc[j][1]);
                    acc[j][1] = fmaf(qv.y, kv1.y, acc[j][1]);
                    acc[j][1] = fmaf(qv.z, kv1.z, acc[j][1]);
                    acc[j][1] = fmaf(qv.w, kv1.w, acc[j][1]);
                    acc[j][2] = fmaf(qv.x, kv2.x, acc[j][2]);
                    acc[j][2] = fmaf(qv.y, kv2.y, acc[j][2]);
                    acc[j][2] = fmaf(qv.z, kv2.z, acc[j][2]);
                    acc[j][2] = fmaf(qv.w, kv2.w, acc[j][2]);
                    acc[j][3] = fmaf(qv.x, kv3.x, acc[j][3]);
                    acc[j][3] = fmaf(qv.y, kv3.y, acc[j][3]);
                    acc[j][3] = fmaf(qv.z, kv3.z, acc[j][3]);
                    acc[j][3] = fmaf(qv.w, kv3.w, acc[j][3]);
                }
            }
        }

        // Write sim tile (conflict-free: bank = (4qg + j + kg) mod 32)
#pragma unroll
        for (int j = 0; j < 4; j++)
#pragma unroll
            for (int i = 0; i < 4; i++)
                simbuf[(qg * 4 + j) * 129 + (kg + 32 * i)] = acc[j][i];
        __syncthreads();

        // Streaming top-32 update: one thread per query row.
        // Strict > on insert keeps earlier (lower-index) candidates on ties.
        // Eviction rescan prefers the LARGEST index among equal minima, so
        // lower-index equal values survive (jax.lax.top_k semantics).
        if (t < 32) {
            const float* sv = simbuf + t * 129;
            float* lv = tkv + t * 33;
            int*   li = tki + t * 33;
            for (int cand = 0; cand < 128; cand++) {
                float v = sv[cand];
                if (v > mv) {
                    lv[mp] = v;
                    li[mp] = kt + cand;
                    // rescan for new min (tie-break: largest index)
                    mv = lv[0]; mp = 0; mi = li[0];
#pragma unroll
                    for (int s = 1; s < 32; s++) {
                        float u  = lv[s];
                        int   ui = li[s];
                        if (u < mv || (u == mv && ui > mi)) { mv = u; mp = s; mi = ui; }
                    }
                }
            }
        }
    }

    __syncthreads();
    if (t < 32) {
        size_t row = (size_t)b * Nn + q0g + t;
#pragma unroll
        for (int s = 0; s < 32; s++) {
            g_tkv[row * 32 + s] = tkv[t * 33 + s];
            g_tki[row * 32 + s] = tki[t * 33 + s];
        }
    }
}

// ---------------------------------------------------------------------------
// Kernel 4: softmax over top-32 sims + gather-weighted feature sum.
// One block per (b, n) row; thread = output channel.
// ---------------------------------------------------------------------------
__global__ __launch_bounds__(256) void k_epilogue(float* __restrict__ out) {
    __shared__ float wv[32];
    __shared__ int   id[32];
    __shared__ float ev[32];
    const int row = blockIdx.x;         // b*N + n
    const int b   = row >> 12;          // /4096
    const int c   = threadIdx.x;

    if (c < 32) {
        wv[c] = g_tkv[(size_t)row * 32 + c];
        id[c] = g_tki[(size_t)row * 32 + c];
    }
    __syncthreads();

    float m = -1e30f;
#pragma unroll
    for (int s = 0; s < 32; s++) m = fmaxf(m, wv[s]);
    if (c < 32) ev[c] = expf(wv[c] - m);
    __syncthreads();

    float sum = 0.f;
#pragma unroll
    for (int s = 0; s < 32; s++) sum += ev[s];

    const float* feat = g_feat + (size_t)b * Nn * Cc;
    float acc = 0.f;
#pragma unroll
    for (int s = 0; s < 32; s++)
        acc += ev[s] * feat[(size_t)id[s] * Cc + c];

    out[(size_t)row * Cc + c] = acc / sum;
}

// ---------------------------------------------------------------------------
extern "C" void kernel_launch(void* const* d_in, const int* in_sizes, int n_in,
                              void* d_out, int out_size) {
    const float* x    = (const float*)d_in[0];
    const float* W    = (const float*)d_in[1];
    const float* bias = (const float*)d_in[2];
    // d_in[3] is k; shapes are compile-time constants here (K=32).
    float* out = (float*)d_out;

    k_gemm<<<dim3(ROWS / 128, 512 / 128), 256>>>(x, W, bias);
    k_normalize<<<ROWS / 8, 256>>>();

    const size_t shmem = 23136 * sizeof(float);  // 92544 B
    cudaFuncSetAttribute(k_sim_topk, cudaFuncAttributeMaxDynamicSharedMemorySize,
                         (int)shmem);
    k_sim_topk<<<dim3(Nn / 32, Bb), 256, shmem>>>();

    k_epilogue<<<ROWS, 256>>>(out);
}

// round 10
// speedup vs baseline: 1.0247x; 1.0247x over previous
#include <cuda_runtime.h>
#include <math.h>

#define Bb 8
#define Nn 4096
#define Cc 256
#define Kk 32
#define ROWS (Bb * Nn)

// Scratch (allocation-free rule: __device__ globals)
__device__ float g_feat[ROWS * Cc];   // 32 MB
__device__ float g_pos [ROWS * Cc];   // 32 MB
__device__ float g_tkv [ROWS * Kk];   // 4 MB
__device__ int   g_tki [ROWS * Kk];   // 4 MB

// ---------------------------------------------------------------------------
// Kernel 1: feat_pos = x @ W^T + bias -> g_feat / g_pos. Sequential k-order
// FMA chain per output element (correlates rounding with reference GEMM).
// ---------------------------------------------------------------------------
__global__ __launch_bounds__(256) void k_gemm(const float* __restrict__ x,
                                              const float* __restrict__ W,
                                              const float* __restrict__ bias) {
    __shared__ float as[128][17];
    __shared__ float bs[128][17];
    const int t  = threadIdx.x;
    const int tx = t & 15;
    const int ty = t >> 4;
    const int m0 = blockIdx.x * 128;
    const int n0 = blockIdx.y * 128;
    const float* xa = x + (size_t)m0 * Cc;
    const float* wb = W + (size_t)n0 * Cc;

    float acc[8][8];
#pragma unroll
    for (int j = 0; j < 8; j++)
#pragma unroll
        for (int i = 0; i < 8; i++) acc[j][i] = 0.f;

    for (int c0 = 0; c0 < Cc; c0 += 16) {
#pragma unroll
        for (int r = 0; r < 8; r++) {
            int lin = t + r * 256;
            int row = lin >> 4;
            int cc  = lin & 15;
            as[row][cc] = xa[row * Cc + c0 + cc];
            bs[row][cc] = wb[row * Cc + c0 + cc];
        }
        __syncthreads();
#pragma unroll
        for (int c = 0; c < 16; c++) {
            float av[8], bv[8];
#pragma unroll
            for (int j = 0; j < 8; j++) av[j] = as[ty + 16 * j][c];
#pragma unroll
            for (int i = 0; i < 8; i++) bv[i] = bs[tx + 16 * i][c];
#pragma unroll
            for (int j = 0; j < 8; j++)
#pragma unroll
                for (int i = 0; i < 8; i++) acc[j][i] = fmaf(av[j], bv[i], acc[j][i]);
        }
        __syncthreads();
    }

#pragma unroll
    for (int j = 0; j < 8; j++) {
        int row = m0 + ty + 16 * j;
#pragma unroll
        for (int i = 0; i < 8; i++) {
            int col = n0 + tx + 16 * i;
            float v = acc[j][i] + bias[col];
            if (col < Cc) g_feat[(size_t)row * Cc + col] = v;
            else          g_pos [(size_t)row * Cc + (col - Cc)] = v;
        }
    }
}

// ---------------------------------------------------------------------------
// Kernel 2: L2-normalize rows of g_pos (divide-by-norm: matches reference).
// ---------------------------------------------------------------------------
__global__ __launch_bounds__(256) void k_normalize() {
    const int row  = blockIdx.x * 8 + (threadIdx.x >> 5);
    const int lane = threadIdx.x & 31;
    float4* p = reinterpret_cast<float4*>(g_pos + (size_t)row * Cc);
    float4 a = p[lane];
    float4 b = p[lane + 32];
    float s = a.x * a.x + a.y * a.y + a.z * a.z + a.w * a.w
            + b.x * b.x + b.y * b.y + b.z * b.z + b.w * b.w;
#pragma unroll
    for (int o = 16; o > 0; o >>= 1) s += __shfl_xor_sync(0xffffffffu, s, o);
    float nrm = fmaxf(sqrtf(s), 1e-12f);
    a.x /= nrm; a.y /= nrm; a.z /= nrm; a.w /= nrm;
    b.x /= nrm; b.y /= nrm; b.z /= nrm; b.w /= nrm;
    p[lane]      = a;
    p[lane + 32] = b;
}

// ---------------------------------------------------------------------------
// Kernel 3: fused sim GEMM + streaming top-32.  v2: 4q x 8k micro-tile.
// Block = 32 queries x 256-key tiles, 256 threads (qg = t>>5, kg = t&31;
// thread covers queries qg*4+j, keys kg+32*i, i<8).
// Per c4-iter: 12 LDS.128 per 128 fmaf = 1.5 B/FMA -> FMA-bound w/ margin.
// Arithmetic UNCHANGED vs passing round: strict ascending-channel fmaf chain
// per (q,k); candidate insertion in ascending global key order; jax tie rules.
// Dynamic smem (floats):
//   qs    [32][256] @ 0      (8192)
//   ks    [256][36] @ 8192   (9216)   pad 36 -> conflict-free LDS.128
//   simbuf[32][260] @ 17408  (8320)   pad 260 -> conflict-free scans
//   tkv   [32][33]  @ 25728  (1056)
//   tki   [32][33]  @ 26784  (1056)
// total 27840 floats = 111360 B  (2 blocks/SM: 222.7 KB <= 228 KB)
// ---------------------------------------------------------------------------
__global__ __launch_bounds__(256) void k_sim_topk() {
    extern __shared__ float sm[];
    float* qs     = sm;
    float* ks     = sm + 8192;
    float* simbuf = sm + 17408;
    float* tkv    = sm + 25728;
    int*   tki    = (int*)(sm + 26784);

    const int t   = threadIdx.x;
    const int b   = blockIdx.y;
    const int q0g = blockIdx.x * 32;
    const float* __restrict__ pos = g_pos + (size_t)b * Nn * Cc;

    // Stage query tile
    for (int lin = t; lin < 32 * Cc; lin += 256)
        qs[lin] = pos[(size_t)q0g * Cc + lin];

    float mv = -1e30f;     // current min value in top-k buffer
    int   mp = 0;          // its slot
    int   mi = 0x7fffffff; // its candidate index (tie-break)
    if (t < 32) {
#pragma unroll
        for (int s = 0; s < 32; s++) { tkv[t * 33 + s] = -1e30f; tki[t * 33 + s] = 0x7fffffff; }
    }

    const int qg = t >> 5;   // 0..7
    const int kg = t & 31;   // 0..31

    for (int kt = 0; kt < Nn; kt += 256) {
        float acc[4][8];
#pragma unroll
        for (int j = 0; j < 4; j++)
#pragma unroll
            for (int i = 0; i < 8; i++) acc[j][i] = 0.f;

        for (int cc = 0; cc < Cc; cc += 32) {
            __syncthreads();   // protects ks reuse + simbuf from prior scan
            // Stage key chunk: 256 keys x 32 channels (2048 float4, 8/thread)
#pragma unroll
            for (int r = 0; r < 8; r++) {
                int lin = t + r * 256;            // 0..2047
                int kk  = lin >> 3;               // 0..255
                int c4  = (lin & 7) << 2;         // 0..28
                float4 v = *(const float4*)(pos + (size_t)(kt + kk) * Cc + cc + c4);
                *(float4*)(ks + kk * 36 + c4) = v;
            }
            __syncthreads();
#pragma unroll
            for (int c = 0; c < 32; c += 4) {
                float4 kv[8];
#pragma unroll
                for (int i = 0; i < 8; i++)
                    kv[i] = *(const float4*)(ks + (kg + 32 * i) * 36 + c);
#pragma unroll
                for (int j = 0; j < 4; j++) {
                    float4 qv = *(const float4*)(qs + (qg * 4 + j) * Cc + cc + c);
#pragma unroll
                    for (int i = 0; i < 8; i++) {
                        // strict sequential channel-order chain per (q,k)
                        acc[j][i] = fmaf(qv.x, kv[i].x, acc[j][i]);
                        acc[j][i] = fmaf(qv.y, kv[i].y, acc[j][i]);
                        acc[j][i] = fmaf(qv.z, kv[i].z, acc[j][i]);
                        acc[j][i] = fmaf(qv.w, kv[i].w, acc[j][i]);
                    }
                }
            }
        }

        // Write sim tile (lanes kg consecutive -> conflict-free STS)
#pragma unroll
        for (int j = 0; j < 4; j++)
#pragma unroll
            for (int i = 0; i < 8; i++)
                simbuf[(qg * 4 + j) * 260 + (kg + 32 * i)] = acc[j][i];
        __syncthreads();

        // Streaming top-32: one owner thread per query; float4 scan with
        // max-of-4 early reject. Candidates processed in ascending index
        // order (x,y,z,w) -> identical selection to passing round.
        if (t < 32) {
            const float* sv = simbuf + t * 260;
            float* lv = tkv + t * 33;
            int*   li = tki + t * 33;
            for (int c4 = 0; c4 < 256; c4 += 4) {
                float4 v4 = *(const float4*)(sv + c4);
                float m4 = fmaxf(fmaxf(v4.x, v4.y), fmaxf(v4.z, v4.w));
                if (m4 > mv) {
#pragma unroll
                    for (int u = 0; u < 4; u++) {
                        float v = (u == 0) ? v4.x : (u == 1) ? v4.y : (u == 2) ? v4.z : v4.w;
                        if (v > mv) {
                            lv[mp] = v;
                            li[mp] = kt + c4 + u;
                            // rescan for new min (tie-break: largest index)
                            mv = lv[0]; mp = 0; mi = li[0];
#pragma unroll
                            for (int s = 1; s < 32; s++) {
                                float w  = lv[s];
                                int   wi = li[s];
                                if (w < mv || (w == mv && wi > mi)) { mv = w; mp = s; mi = wi; }
                            }
                        }
                    }
                }
            }
        }
    }

    __syncthreads();
    if (t < 32) {
        size_t row = (size_t)b * Nn + q0g + t;
#pragma unroll
        for (int s = 0; s < 32; s++) {
            g_tkv[row * 32 + s] = tkv[t * 33 + s];
            g_tki[row * 32 + s] = tki[t * 33 + s];
        }
    }
}

// ---------------------------------------------------------------------------
// Kernel 4: softmax over top-32 sims + gather-weighted feature sum.
// ---------------------------------------------------------------------------
__global__ __launch_bounds__(256) void k_epilogue(float* __restrict__ out) {
    __shared__ float wv[32];
    __shared__ int   id[32];
    __shared__ float ev[32];
    const int row = blockIdx.x;
    const int b   = row >> 12;
    const int c   = threadIdx.x;

    if (c < 32) {
        wv[c] = g_tkv[(size_t)row * 32 + c];
        id[c] = g_tki[(size_t)row * 32 + c];
    }
    __syncthreads();

    float m = -1e30f;
#pragma unroll
    for (int s = 0; s < 32; s++) m = fmaxf(m, wv[s]);
    if (c < 32) ev[c] = expf(wv[c] - m);
    __syncthreads();

    float sum = 0.f;
#pragma unroll
    for (int s = 0; s < 32; s++) sum += ev[s];

    const float* feat = g_feat + (size_t)b * Nn * Cc;
    float acc = 0.f;
#pragma unroll
    for (int s = 0; s < 32; s++)
        acc += ev[s] * feat[(size_t)id[s] * Cc + c];

    out[(size_t)row * Cc + c] = acc / sum;
}

// ---------------------------------------------------------------------------
extern "C" void kernel_launch(void* const* d_in, const int* in_sizes, int n_in,
                              void* d_out, int out_size) {
    const float* x    = (const float*)d_in[0];
    const float* W    = (const float*)d_in[1];
    const float* bias = (const float*)d_in[2];
    float* out = (float*)d_out;

    k_gemm<<<dim3(ROWS / 128, 512 / 128), 256>>>(x, W, bias);
    k_normalize<<<ROWS / 8, 256>>>();

    const size_t shmem = 27840 * sizeof(float);  // 111360 B
    cudaFuncSetAttribute(k_sim_topk, cudaFuncAttributeMaxDynamicSharedMemorySize,
                         (int)shmem);
    k_sim_topk<<<dim3(Nn / 32, Bb), 256, shmem>>>();

    k_epilogue<<<ROWS, 256>>>(out);
}